// round 9
// baseline (speedup 1.0000x reference)
#include <cuda_runtime.h>

// ---------------------------------------------------------------------------
// Threshold_weights7: per-row top-2 margins over 8 predictors [N,128],
// softmax(margins/2) over 8 predictors, plus global max of predictors 0..6.
// Memory-bound: 512MB read. TWO rows per warp (16 lanes each). Batch 0
// (preds 0-3) loads to registers; batch 1 (preds 4-7) streams via cp.async.cg
// into smem concurrently -> 16 loads in flight at burst, compute phases fully
// covered. Single kernel, last-block finalize.
// ---------------------------------------------------------------------------

static constexpr int kC = 128;  // class dim

__device__ unsigned g_max_key;  // zero-init at load; self-reset every call
__device__ unsigned g_ticket;

__device__ __forceinline__ unsigned f2key(float f) {
    unsigned u = __float_as_uint(f);
    return (u & 0x80000000u) ? ~u : (u | 0x80000000u);
}

__device__ __forceinline__ void cp_async16(void* smem_dst, const void* gsrc) {
    unsigned saddr = (unsigned)__cvta_generic_to_shared(smem_dst);
    asm volatile("cp.async.cg.shared.global [%0], [%1], 16;\n"
                 :: "r"(saddr), "l"(gsrc) : "memory");
}

__global__ void __launch_bounds__(256, 4)
k_main(const float* __restrict__ p0, const float* __restrict__ p1,
       const float* __restrict__ p2, const float* __restrict__ p3,
       const float* __restrict__ p4, const float* __restrict__ p5,
       const float* __restrict__ p6, const float* __restrict__ p7,
       const int* __restrict__ targets,
       float* __restrict__ out,   // [has_scalar + N*8]
       int nrows, int has_scalar)
{
    // batch-1 staging: 8 slots (preds 4-7 x {lo,hi}) x 256 threads x 16B = 32KB
    __shared__ float4 s_buf[8][256];
    __shared__ unsigned s_gm[8];

    const int tid  = threadIdx.x;
    const int lane = tid & 31;
    const int wib  = tid >> 5;                      // warp in block (0..7)
    const int half = lane >> 4;                     // 0: row A, 1: row B
    const int hl   = lane & 15;                     // lane within half

    const int gwarp  = blockIdx.x * 8 + wib;
    const int nwarps = gridDim.x * 8;

    float* __restrict__ thr = out + has_scalar;
    const float* predsA[4] = {p0, p1, p2, p3};
    const float* predsB[4] = {p4, p5, p6, p7};

    float gm = -3.402823466e38f;   // running max over predictors 0..6

    const int npairs = (nrows + 1) >> 1;
    for (int pair = gwarp; pair < npairs; pair += nwarps) {
        const int row = pair * 2 + half;
        const bool rowok = (row < nrows);
        const int rsafe = rowok ? row : (nrows - 1);

        const int t = __ldg(targets + rsafe);
        const int towner = t >> 3;       // lane-in-half holding the target
        const int tq     = (t >> 2) & 1; // which float4
        const int tsub   = t & 3;        // element within float4

        const size_t base = (size_t)rsafe * kC + hl * 8;

        // ---- issue ALL loads up front: 8 LDG.128 (regs) + 8 cp.async (smem)
        float4 va[4], vb[4];
#pragma unroll
        for (int p = 0; p < 4; p++) {
            const float* pr = predsA[p];
            va[p] = __ldcs(reinterpret_cast<const float4*>(pr + base));
            vb[p] = __ldcs(reinterpret_cast<const float4*>(pr + base + 4));
        }
#pragma unroll
        for (int p = 0; p < 4; p++) {
            const float* pr = predsB[p];
            cp_async16(&s_buf[p * 2 + 0][tid], pr + base);
            cp_async16(&s_buf[p * 2 + 1][tid], pr + base + 4);
        }
        asm volatile("cp.async.commit_group;\n" ::: "memory");

        float m[8];

        // ---- compute batch 0 from registers (cp.asyncs in flight) ----
#pragma unroll
        for (int p = 0; p < 4; p++) {
            const float4 qa = va[p], qb = vb[p];
            float a1 = fmaxf(qa.x, qa.y), a2 = fminf(qa.x, qa.y);
            float b1 = fmaxf(qa.z, qa.w), b2 = fminf(qa.z, qa.w);
            float m1a = fmaxf(a1, b1);
            float m2a = fmaxf(fminf(a1, b1), fmaxf(a2, b2));
            float c1 = fmaxf(qb.x, qb.y), c2 = fminf(qb.x, qb.y);
            float d1 = fmaxf(qb.z, qb.w), d2 = fminf(qb.z, qb.w);
            float m1b = fmaxf(c1, d1);
            float m2b = fmaxf(fminf(c1, d1), fmaxf(c2, d2));
            float m1 = fmaxf(m1a, m1b);
            float m2 = fmaxf(fminf(m1a, m1b), fmaxf(m2a, m2b));

            float ta = (tsub == 0) ? qa.x : (tsub == 1) ? qa.y
                     : (tsub == 2) ? qa.z : qa.w;
            float tb = (tsub == 0) ? qb.x : (tsub == 1) ? qb.y
                     : (tsub == 2) ? qb.z : qb.w;
            float tl = tq ? tb : ta;
            float tv = __shfl_sync(0xffffffffu, tl, towner, 16);

#pragma unroll
            for (int off = 8; off; off >>= 1) {
                float o1 = __shfl_xor_sync(0xffffffffu, m1, off);
                float o2 = __shfl_xor_sync(0xffffffffu, m2, off);
                float n2 = fmaxf(fminf(m1, o1), fmaxf(m2, o2));
                m1 = fmaxf(m1, o1);
                m2 = n2;
            }
            m[p] = (tv == m1) ? (m1 - m2) : 0.0f;  // exact tie semantics
            if (rowok) gm = fmaxf(gm, m1);         // preds 0-3 all count
        }

        // ---- batch 1 from smem (each thread reads its own slots) ----
        asm volatile("cp.async.wait_group 0;\n" ::: "memory");
#pragma unroll
        for (int p = 0; p < 4; p++) {
            const float4 qa = s_buf[p * 2 + 0][tid];
            const float4 qb = s_buf[p * 2 + 1][tid];
            float a1 = fmaxf(qa.x, qa.y), a2 = fminf(qa.x, qa.y);
            float b1 = fmaxf(qa.z, qa.w), b2 = fminf(qa.z, qa.w);
            float m1a = fmaxf(a1, b1);
            float m2a = fmaxf(fminf(a1, b1), fmaxf(a2, b2));
            float c1 = fmaxf(qb.x, qb.y), c2 = fminf(qb.x, qb.y);
            float d1 = fmaxf(qb.z, qb.w), d2 = fminf(qb.z, qb.w);
            float m1b = fmaxf(c1, d1);
            float m2b = fmaxf(fminf(c1, d1), fmaxf(c2, d2));
            float m1 = fmaxf(m1a, m1b);
            float m2 = fmaxf(fminf(m1a, m1b), fmaxf(m2a, m2b));

            float ta = (tsub == 0) ? qa.x : (tsub == 1) ? qa.y
                     : (tsub == 2) ? qa.z : qa.w;
            float tb = (tsub == 0) ? qb.x : (tsub == 1) ? qb.y
                     : (tsub == 2) ? qb.z : qb.w;
            float tl = tq ? tb : ta;
            float tv = __shfl_sync(0xffffffffu, tl, towner, 16);

#pragma unroll
            for (int off = 8; off; off >>= 1) {
                float o1 = __shfl_xor_sync(0xffffffffu, m1, off);
                float o2 = __shfl_xor_sync(0xffffffffu, m2, off);
                float n2 = fmaxf(fminf(m1, o1), fmaxf(m2, o2));
                m1 = fmaxf(m1, o1);
                m2 = n2;
            }
            m[4 + p] = (tv == m1) ? (m1 - m2) : 0.0f;
            if (p < 3 && rowok) gm = fmaxf(gm, m1);  // pred 7 (mimic): no gm
        }

        // ---- softmax over 8 margins, T=2 ----
        float mm = m[0];
#pragma unroll
        for (int p = 1; p < 8; p++) mm = fmaxf(mm, m[p]);
        float e[8], s = 0.0f;
#pragma unroll
        for (int p = 0; p < 8; p++) { e[p] = __expf((m[p] - mm) * 0.5f); s += e[p]; }
        const float inv = 1.0f / s;

        if (hl < 8 && rowok) {
            float mine = (hl == 0) ? e[0] : (hl == 1) ? e[1]
                       : (hl == 2) ? e[2] : (hl == 3) ? e[3]
                       : (hl == 4) ? e[4] : (hl == 5) ? e[5]
                       : (hl == 6) ? e[6] : e[7];
            thr[(size_t)row * 8 + hl] = mine * inv;
        }
    }

    // ---- global-max finalize (last-block ticket) ----
    gm = fmaxf(gm, __shfl_xor_sync(0xffffffffu, gm, 16));
    if (lane == 0) s_gm[wib] = f2key(gm);
    __syncthreads();
    if (threadIdx.x == 0) {
        unsigned k = s_gm[0];
#pragma unroll
        for (int i = 1; i < 8; i++) k = max(k, s_gm[i]);
        atomicMax(&g_max_key, k);
        __threadfence();
        unsigned old = atomicAdd(&g_ticket, 1u);
        if (old == gridDim.x - 1) {
            unsigned kk = g_max_key;
            if (has_scalar) {
                unsigned u = (kk & 0x80000000u) ? (kk & 0x7FFFFFFFu) : ~kk;
                out[0] = __uint_as_float(u);
            }
            g_max_key = 0u;   // reset for next graph replay
            g_ticket  = 0u;
        }
    }
}

extern "C" void kernel_launch(void* const* d_in, const int* in_sizes, int n_in,
                              void* d_out, int out_size)
{
    const float* p[8];
    for (int i = 0; i < 8; i++) p[i] = (const float*)d_in[i];
    const int* targets = (const int*)d_in[8];
    const int nrows = in_sizes[8];           // targets element count == N

    float* out = (float*)d_out;
    int has_scalar = out_size - nrows * 8;
    if (has_scalar < 0) has_scalar = 0;

    k_main<<<2048, 256>>>(p[0], p[1], p[2], p[3], p[4], p[5], p[6], p[7],
                          targets, out, nrows, has_scalar);
}

// round 11
// speedup vs baseline: 1.2768x; 1.2768x over previous
#include <cuda_runtime.h>

// ---------------------------------------------------------------------------
// Threshold_weights7: per-row top-2 margins over 8 predictors [N,128],
// softmax(margins/2) over 8 predictors, plus global max of predictors 0..6.
// Memory-bound: 512MB read; measured chip ceiling ~6.15 TB/s (LTS cap @ NAT
// clock). R4 structure (best): TWO rows per warp, 2 reg-batches of 4 preds,
// 4 blocks/SM. This round: persistent grid (148*4 blocks, single wave).
// ---------------------------------------------------------------------------

static constexpr int kC = 128;  // class dim
static constexpr int kGrid = 592;  // 148 SMs x 4 blocks/SM, single wave

__device__ unsigned g_max_key;  // zero-init at load; self-reset every call
__device__ unsigned g_ticket;

__device__ __forceinline__ unsigned f2key(float f) {
    unsigned u = __float_as_uint(f);
    return (u & 0x80000000u) ? ~u : (u | 0x80000000u);
}

__global__ void __launch_bounds__(256, 4)
k_main(const float* __restrict__ p0, const float* __restrict__ p1,
       const float* __restrict__ p2, const float* __restrict__ p3,
       const float* __restrict__ p4, const float* __restrict__ p5,
       const float* __restrict__ p6, const float* __restrict__ p7,
       const int* __restrict__ targets,
       float* __restrict__ out,   // [has_scalar + N*8]
       int nrows, int has_scalar)
{
    __shared__ unsigned s_gm[8];

    const int lane = threadIdx.x & 31;
    const int wib  = threadIdx.x >> 5;              // warp in block (0..7)
    const int half = lane >> 4;                     // 0: row A, 1: row B
    const int hl   = lane & 15;                     // lane within half

    const int gwarp  = blockIdx.x * 8 + wib;
    const int nwarps = gridDim.x * 8;

    float* __restrict__ thr = out + has_scalar;
    const float* preds[8] = {p0, p1, p2, p3, p4, p5, p6, p7};

    float gm = -3.402823466e38f;   // running max over predictors 0..6

    const int npairs = (nrows + 1) >> 1;
    for (int pair = gwarp; pair < npairs; pair += nwarps) {
        const int row = pair * 2 + half;
        const bool rowok = (row < nrows);
        const int rsafe = rowok ? row : (nrows - 1);

        const int t = __ldg(targets + rsafe);
        const int towner = t >> 3;       // lane-in-half holding the target
        const int tq     = (t >> 2) & 1; // which float4
        const int tsub   = t & 3;        // element within float4

        const size_t base = (size_t)rsafe * kC + hl * 8;

        float m[8];

        // Two batches of 4 predictors: 8 LDG.128 in flight per batch,
        // 32 data regs -> 4 blocks/SM.
#pragma unroll
        for (int b = 0; b < 2; b++) {
            float4 va[4], vb[4];
#pragma unroll
            for (int p = 0; p < 4; p++) {
                const float* pr = preds[b * 4 + p];
                va[p] = __ldcs(reinterpret_cast<const float4*>(pr + base));
                vb[p] = __ldcs(reinterpret_cast<const float4*>(pr + base + 4));
            }

#pragma unroll
            for (int p = 0; p < 4; p++) {
                const float4 qa = va[p], qb = vb[p];
                // lane-local top-2 of 8 values
                float a1 = fmaxf(qa.x, qa.y), a2 = fminf(qa.x, qa.y);
                float b1 = fmaxf(qa.z, qa.w), b2 = fminf(qa.z, qa.w);
                float m1a = fmaxf(a1, b1);
                float m2a = fmaxf(fminf(a1, b1), fmaxf(a2, b2));
                float c1 = fmaxf(qb.x, qb.y), c2 = fminf(qb.x, qb.y);
                float d1 = fmaxf(qb.z, qb.w), d2 = fminf(qb.z, qb.w);
                float m1b = fmaxf(c1, d1);
                float m2b = fmaxf(fminf(c1, d1), fmaxf(c2, d2));
                float m1 = fmaxf(m1a, m1b);
                float m2 = fmaxf(fminf(m1a, m1b), fmaxf(m2a, m2b));

                // target logit: element tsub of float4 tq from lane towner
                float ta = (tsub == 0) ? qa.x : (tsub == 1) ? qa.y
                         : (tsub == 2) ? qa.z : qa.w;
                float tb = (tsub == 0) ? qb.x : (tsub == 1) ? qb.y
                         : (tsub == 2) ? qb.z : qb.w;
                float tl = tq ? tb : ta;
                float tv = __shfl_sync(0xffffffffu, tl, towner, 16);

                // 4-step butterfly top-2 merge within the 16-lane half
#pragma unroll
                for (int off = 8; off; off >>= 1) {
                    float o1 = __shfl_xor_sync(0xffffffffu, m1, off);
                    float o2 = __shfl_xor_sync(0xffffffffu, m2, off);
                    float n2 = fmaxf(fminf(m1, o1), fmaxf(m2, o2));
                    m1 = fmaxf(m1, o1);
                    m2 = n2;
                }
                // margin: exact-equality tie semantics of the reference
                m[b * 4 + p] = (tv == m1) ? (m1 - m2) : 0.0f;
                if ((b * 4 + p) < 7 && rowok) gm = fmaxf(gm, m1);
            }
        }

        // softmax over the 8 margins, T=2 (redundant across the half; cheap)
        float mm = m[0];
#pragma unroll
        for (int p = 1; p < 8; p++) mm = fmaxf(mm, m[p]);
        float e[8], s = 0.0f;
#pragma unroll
        for (int p = 0; p < 8; p++) { e[p] = __expf((m[p] - mm) * 0.5f); s += e[p]; }
        const float inv = 1.0f / s;

        if (hl < 8 && rowok) {
            float mine = (hl == 0) ? e[0] : (hl == 1) ? e[1]
                       : (hl == 2) ? e[2] : (hl == 3) ? e[3]
                       : (hl == 4) ? e[4] : (hl == 5) ? e[5]
                       : (hl == 6) ? e[6] : e[7];
            thr[(size_t)row * 8 + hl] = mine * inv;
        }
    }

    // ---- global-max finalize in the same kernel (last-block ticket) ----
    gm = fmaxf(gm, __shfl_xor_sync(0xffffffffu, gm, 16));  // merge both halves
    if (lane == 0) s_gm[wib] = f2key(gm);
    __syncthreads();
    if (threadIdx.x == 0) {
        unsigned k = s_gm[0];
#pragma unroll
        for (int i = 1; i < 8; i++) k = max(k, s_gm[i]);
        atomicMax(&g_max_key, k);
        __threadfence();
        unsigned old = atomicAdd(&g_ticket, 1u);
        if (old == gridDim.x - 1) {
            unsigned kk = g_max_key;
            if (has_scalar) {
                unsigned u = (kk & 0x80000000u) ? (kk & 0x7FFFFFFFu) : ~kk;
                out[0] = __uint_as_float(u);
            }
            g_max_key = 0u;   // reset for next graph replay
            g_ticket  = 0u;
        }
    }
}

extern "C" void kernel_launch(void* const* d_in, const int* in_sizes, int n_in,
                              void* d_out, int out_size)
{
    const float* p[8];
    for (int i = 0; i < 8; i++) p[i] = (const float*)d_in[i];
    const int* targets = (const int*)d_in[8];
    const int nrows = in_sizes[8];           // targets element count == N

    float* out = (float*)d_out;
    int has_scalar = out_size - nrows * 8;
    if (has_scalar < 0) has_scalar = 0;

    k_main<<<kGrid, 256>>>(p[0], p[1], p[2], p[3], p[4], p[5], p[6], p[7],
                           targets, out, nrows, has_scalar);
}